// round 13
// baseline (speedup 1.0000x reference)
#include <cuda_runtime.h>
#include <cuda_fp16.h>
#include <stdint.h>
#include <math.h>

#define B_DIM 8
#define C_DIM 256
#define H_DIM 128
#define W_DIM 128
#define HW    (H_DIM * W_DIM)
#define NTOK  (B_DIM * HW)
#define QK_SCALE 0.0625f

// X fp16 c-major: [c][token]
__device__ __half g_x[C_DIM * NTOK];
// T = X*M and V = X*Wv + bv, fp16 [token][channel]
__device__ __half g_t[NTOK * C_DIM];
__device__ __half g_v[NTOK * C_DIM];
// Wv fp16 [o][c]; Mt[c'][c] = scale * sum_o Wq[o,c] Wk[o,c'] fp16; u fp32
__device__ __half g_wv[C_DIM * C_DIM];
__device__ __half g_mt[C_DIM * C_DIM];
__device__ float  g_u[C_DIM];

__device__ __forceinline__ uint32_t smem_u32(const void* p) {
    uint32_t a;
    asm("{ .reg .u64 t; cvta.to.shared.u64 t, %1; cvt.u32.u64 %0, t; }" : "=r"(a) : "l"(p));
    return a;
}
__device__ __forceinline__ void cp16(uint32_t dst, const void* src) {
    asm volatile("cp.async.cg.shared.global [%0], [%1], 16;" :: "r"(dst), "l"(src));
}
__device__ __forceinline__ void cp_commit() { asm volatile("cp.async.commit_group;" ::: "memory"); }
__device__ __forceinline__ void cp_wait2()  { asm volatile("cp.async.wait_group 2;" ::: "memory"); }
__device__ __forceinline__ void cp_wait1()  { asm volatile("cp.async.wait_group 1;" ::: "memory"); }
__device__ __forceinline__ void cp_wait0()  { asm volatile("cp.async.wait_group 0;" ::: "memory"); }

__device__ __forceinline__ void ldm_x4(uint32_t& r0, uint32_t& r1, uint32_t& r2, uint32_t& r3, uint32_t addr) {
    asm volatile("ldmatrix.sync.aligned.m8n8.x4.shared.b16 {%0,%1,%2,%3}, [%4];"
                 : "=r"(r0), "=r"(r1), "=r"(r2), "=r"(r3) : "r"(addr));
}
__device__ __forceinline__ void ldm_x4_t(uint32_t& r0, uint32_t& r1, uint32_t& r2, uint32_t& r3, uint32_t addr) {
    asm volatile("ldmatrix.sync.aligned.m8n8.x4.trans.shared.b16 {%0,%1,%2,%3}, [%4];"
                 : "=r"(r0), "=r"(r1), "=r"(r2), "=r"(r3) : "r"(addr));
}
__device__ __forceinline__ void mmaf16(float* c, const uint32_t* a, uint32_t b0, uint32_t b1) {
    asm volatile("mma.sync.aligned.m16n8k16.row.col.f32.f16.f16.f32 "
                 "{%0,%1,%2,%3},{%4,%5,%6,%7},{%8,%9},{%0,%1,%2,%3};"
                 : "+f"(c[0]), "+f"(c[1]), "+f"(c[2]), "+f"(c[3])
                 : "r"(a[0]), "r"(a[1]), "r"(a[2]), "r"(a[3]), "r"(b0), "r"(b1));
}
__device__ __forceinline__ uint32_t pkh(float x, float y) {
    __half2 t = __floats2half2_rn(x, y);
    return *(uint32_t*)&t;
}

// Fused prep: blocks 0..31 compute 8 Mt rows each (+convert 8 wv rows);
// block 32 computes u. wq column reads coalesced; wk broadcast.
__global__ __launch_bounds__(256)
void prep(const float* __restrict__ wq, const float* __restrict__ wk,
          const float* __restrict__ bq, const float* __restrict__ wv)
{
    int blk = blockIdx.x;
    int c = threadIdx.x;
    if (blk < 32) {
        int cp0 = blk * 8;
        float acc[8] = {0.f, 0.f, 0.f, 0.f, 0.f, 0.f, 0.f, 0.f};
        for (int o = 0; o < 256; ++o) {
            float q = wq[o * 256 + c];
            #pragma unroll
            for (int j = 0; j < 8; ++j)
                acc[j] += q * wk[o * 256 + cp0 + j];
        }
        #pragma unroll
        for (int j = 0; j < 8; ++j) {
            g_mt[(cp0 + j) * 256 + c] = __float2half(acc[j] * QK_SCALE);
            g_wv[(cp0 + j) * 256 + c] = __float2half(wv[(cp0 + j) * 256 + c]);
        }
    } else {
        float acc = 0.f;
        for (int o = 0; o < 256; ++o)
            acc += bq[o] * wk[o * 256 + c];
        g_u[c] = acc * QK_SCALE;
    }
}

// a NCHW fp32 -> g_x [c][token] fp16 (coalesced both sides)
__global__ __launch_bounds__(256)
void xconvert(const float* __restrict__ a)
{
    int idx4 = blockIdx.x * 256 + threadIdx.x;
    int b    = idx4 >> 20;
    int rem  = idx4 & 1048575;
    int c    = rem >> 12;
    int hw4  = rem & 4095;
    float4 v = *(const float4*)(a + (size_t)idx4 * 4);
    size_t o = (size_t)c * NTOK + (size_t)b * HW + (size_t)hw4 * 4;
    __half2* ph = (__half2*)(g_x + o);
    ph[0] = __floats2half2_rn(v.x, v.y);
    ph[1] = __floats2half2_rn(v.z, v.w);
}

// ===========================================================================
// T/V GEMM: grid (4,1024). variant: 0,1 = T halves (B=Mt); 2,3 = V halves
// (B=Wv, +bv). CTA 128 tok x 128 out, K=256, 3-stage pipeline.
// ===========================================================================
#define TV_STAGE 32768
#define TV_SMEM  (3 * TV_STAGE)

__global__ __launch_bounds__(256, 2)
void tv_mma(const float* __restrict__ bv)
{
    extern __shared__ char smem[];
    const uint32_t sb = smem_u32(smem);
    const int tid = threadIdx.x, lane = tid & 31, wid = tid >> 5;
    const int wm0 = (wid & 3) * 32;
    const int wn0 = (wid >> 2) * 64;
    const int variant = blockIdx.x;
    const int half = variant & 1;
    const int isV  = variant >> 1;
    const int tok0 = blockIdx.y * 128;

    const __half* xB = g_x + tok0;
    const __half* wB = (isV ? g_wv : g_mt) + half * 128 * 256;

    const int lrowA = tid >> 4, lc16A = tid & 15;
    const int lrowB = tid >> 3, lc16B = tid & 7;

    auto loadIt = [&](int stg, int kc) {
        const uint32_t st = sb + stg * TV_STAGE;
        const __half* As = xB + (size_t)(kc * 64) * NTOK;
        #pragma unroll
        for (int r = 0; r < 4; ++r) {
            int row = r * 16 + lrowA;
            cp16(st + row * 256 + ((lc16A ^ (row & 7)) << 4),
                 As + (size_t)row * NTOK + lc16A * 8);
        }
        const __half* Bs = wB + kc * 64;
        #pragma unroll
        for (int r = 0; r < 4; ++r) {
            int row = r * 32 + lrowB;
            cp16(st + 16384 + row * 128 + ((lc16B ^ (row & 7)) << 4),
                 Bs + row * 256 + lc16B * 8);
        }
    };

    float acc[2][8][4];
    #pragma unroll
    for (int mt = 0; mt < 2; ++mt)
        #pragma unroll
        for (int n8 = 0; n8 < 8; ++n8)
            #pragma unroll
            for (int e = 0; e < 4; ++e) acc[mt][n8][e] = 0.0f;

    loadIt(0, 0); cp_commit();
    loadIt(1, 1); cp_commit();

    for (int kc = 0; kc < 4; ++kc) {
        if (kc < 2) { loadIt((kc + 2) % 3, kc + 2); cp_commit(); }
        if (kc < 2) cp_wait2(); else if (kc == 2) cp_wait1(); else cp_wait0();
        __syncthreads();
        const uint32_t st = sb + (kc % 3) * TV_STAGE;

        #pragma unroll
        for (int ks = 0; ks < 4; ++ks) {
            uint32_t af[2][4];
            const int arow = ks * 16 + (lane & 7) + ((lane >> 4) << 3);
            #pragma unroll
            for (int mt = 0; mt < 2; ++mt) {
                int chunk = (wm0 >> 3) + mt * 2 + ((lane >> 3) & 1);
                uint32_t addr = st + arow * 256 + ((chunk ^ (arow & 7)) << 4);
                ldm_x4_t(af[mt][0], af[mt][1], af[mt][2], af[mt][3], addr);
            }
            const int rbase = (lane & 7) + ((lane >> 3) & 1) * 8;
            const int c16 = ks * 2 + (lane >> 4);
            #pragma unroll
            for (int ng = 0; ng < 4; ++ng) {
                int brow = wn0 + ng * 16 + rbase;
                uint32_t bsw = brow * 128 + ((c16 ^ (brow & 7)) << 4);
                uint32_t b0, b1, b2, b3;
                ldm_x4(b0, b1, b2, b3, st + 16384 + bsw);
                #pragma unroll
                for (int mt = 0; mt < 2; ++mt) {
                    mmaf16(acc[mt][2 * ng],     af[mt], b0, b2);
                    mmaf16(acc[mt][2 * ng + 1], af[mt], b1, b3);
                }
            }
        }
        __syncthreads();
    }

    __half* dst = isV ? g_v : g_t;
    const int g = lane >> 2, t = lane & 3;
    #pragma unroll
    for (int mt = 0; mt < 2; ++mt) {
        size_t r0 = (size_t)(tok0 + wm0 + mt * 16 + g), r1 = r0 + 8;
        #pragma unroll
        for (int n8 = 0; n8 < 8; ++n8) {
            int o = half * 128 + wn0 + n8 * 8 + t * 2;
            float b0v = isV ? bv[o] : 0.0f;
            float b1v = isV ? bv[o + 1] : 0.0f;
            *(uint32_t*)(dst + r0 * 256 + o) = pkh(acc[mt][n8][0] + b0v, acc[mt][n8][1] + b1v);
            *(uint32_t*)(dst + r1 * 256 + o) = pkh(acc[mt][n8][2] + b0v, acc[mt][n8][3] + b1v);
        }
    }
}

// ===========================================================================
// Attention: S = T * X^T + gamma, softmax, O = P * V. One CTA per scanline.
// gamma precomputed from global X up-front; V(0) prefetched under kc=3,
// V(1) under softmax. Stages 2x32KB; Os fp32 @65536; gamma @99328.
// ===========================================================================
#define ATTN_SMEM 99840

__global__ __launch_bounds__(256, 2)
void attn_mma(const float* __restrict__ a, const float* __restrict__ Wp,
              float* __restrict__ out)
{
    extern __shared__ char smem[];
    const uint32_t sb = smem_u32(smem);
    float* Os  = (float*)(smem + 65536);
    float* gam = (float*)(smem + 99328);
    const int tid = threadIdx.x, lane = tid & 31, wid = tid >> 5;
    const int m0 = wid * 16;
    const int bh = blockIdx.x, b = bh >> 7, h = bh & 127;
    const int tok0 = bh * 128;
    const size_t tokbase = (size_t)bh * 128;

    const int lrow = tid >> 3, lc16 = tid & 7;     // T/V tiles
    const int lrowX = tid >> 4, lc16X = tid & 15;  // X tiles

    auto loadTX = [&](int stg, int kc) {
        const uint32_t st = sb + stg * 32768;
        const size_t scol = tokbase * 256 + kc * 64;
        #pragma unroll
        for (int r = 0; r < 4; ++r) {
            int row = r * 32 + lrow;
            uint32_t doff = row * 128 + ((lc16 ^ (row & 7)) << 4);
            cp16(st + doff, g_t + scol + (size_t)row * 256 + lc16 * 8);
        }
        #pragma unroll
        for (int r = 0; r < 4; ++r) {
            int row = r * 16 + lrowX;
            uint32_t doff = row * 256 + ((lc16X ^ (row & 7)) << 4);
            cp16(st + 16384 + doff,
                 g_x + (size_t)(kc * 64 + row) * NTOK + tok0 + lc16X * 8);
        }
    };
    auto loadV = [&](int stg, int cc) {
        const uint32_t st = sb + stg * 32768;
        const size_t scol = tokbase * 256 + cc * 64;
        #pragma unroll
        for (int r = 0; r < 4; ++r) {
            int row = r * 32 + lrow;
            uint32_t doff = row * 128 + ((lc16 ^ (row & 7)) << 4);
            cp16(st + doff, g_v + scol + (size_t)row * 256 + lc16 * 8);
        }
    };

    loadTX(0, 0); cp_commit();

    // gamma precompute: gam[n] = sum_c u[c] * X[c][tok0+n] (coalesced LDG,
    // overlaps the first loadTX's latency)
    float greg = 0.0f;
    if (tid < 128) {
        const __half* xp = g_x + tok0 + tid;
        #pragma unroll 4
        for (int c = 0; c < 256; ++c)
            greg += __half2float(__ldg(xp + (size_t)c * NTOK)) * __ldg(&g_u[c]);
    }

    float sacc[16][4];
    #pragma unroll
    for (int j = 0; j < 16; ++j)
        #pragma unroll
        for (int e = 0; e < 4; ++e) sacc[j][e] = 0.0f;

    for (int kc = 0; kc < 4; ++kc) {
        if (kc < 3) { loadTX((kc + 1) & 1, kc + 1); cp_commit(); }
        cp_wait1();                     // current kc's group done (V0 may stay pending at kc=3)
        __syncthreads();
        const uint32_t st = sb + (kc & 1) * 32768;
        #pragma unroll
        for (int ks = 0; ks < 4; ++ks) {
            uint32_t ah[4];
            const int c16 = ks * 2 + (lane >> 4);
            int arow = m0 + (lane & 15);
            uint32_t aoff = arow * 128 + ((c16 ^ (arow & 7)) << 4);
            ldm_x4(ah[0], ah[1], ah[2], ah[3], st + aoff);
            const int brow = ks * 16 + (lane & 15);
            #pragma unroll
            for (int bn = 0; bn < 8; ++bn) {
                int nchunk = bn * 2 + (lane >> 4);
                uint32_t boff = brow * 256 + ((nchunk ^ (brow & 7)) << 4);
                uint32_t b0, b1, b2, b3;
                ldm_x4_t(b0, b1, b2, b3, st + 16384 + boff);
                mmaf16(sacc[2 * bn],     ah, b0, b1);
                mmaf16(sacc[2 * bn + 1], ah, b2, b3);
            }
        }
        __syncthreads();
        if (kc == 2) { loadV(0, 0); cp_commit(); }   // stage 0 free after kc=2
    }
    // stage 1 free after kc=3 compute; prefetch V(1) under softmax
    loadV(1, 1); cp_commit();
    if (tid < 128) gam[tid] = greg;
    __syncthreads();

    const int g = lane >> 2, t4 = lane & 3;
    #pragma unroll
    for (int j = 0; j < 16; ++j) {
        float ga = gam[j * 8 + t4 * 2], gb = gam[j * 8 + t4 * 2 + 1];
        sacc[j][0] += ga; sacc[j][1] += gb;
        sacc[j][2] += ga; sacc[j][3] += gb;
    }

    float mx0 = -1e30f, mx1 = -1e30f;
    #pragma unroll
    for (int j = 0; j < 16; ++j) {
        mx0 = fmaxf(mx0, fmaxf(sacc[j][0], sacc[j][1]));
        mx1 = fmaxf(mx1, fmaxf(sacc[j][2], sacc[j][3]));
    }
    mx0 = fmaxf(mx0, __shfl_xor_sync(~0u, mx0, 1));
    mx0 = fmaxf(mx0, __shfl_xor_sync(~0u, mx0, 2));
    mx1 = fmaxf(mx1, __shfl_xor_sync(~0u, mx1, 1));
    mx1 = fmaxf(mx1, __shfl_xor_sync(~0u, mx1, 2));
    float sum0 = 0.0f, sum1 = 0.0f;
    #pragma unroll
    for (int j = 0; j < 16; ++j) {
        sacc[j][0] = __expf(sacc[j][0] - mx0); sum0 += sacc[j][0];
        sacc[j][1] = __expf(sacc[j][1] - mx0); sum0 += sacc[j][1];
        sacc[j][2] = __expf(sacc[j][2] - mx1); sum1 += sacc[j][2];
        sacc[j][3] = __expf(sacc[j][3] - mx1); sum1 += sacc[j][3];
    }
    sum0 += __shfl_xor_sync(~0u, sum0, 1);
    sum0 += __shfl_xor_sync(~0u, sum0, 2);
    sum1 += __shfl_xor_sync(~0u, sum1, 1);
    sum1 += __shfl_xor_sync(~0u, sum1, 2);
    const float inv0 = 1.0f / sum0, inv1 = 1.0f / sum1;

    uint32_t phi[8][4];
    #pragma unroll
    for (int kt = 0; kt < 8; ++kt) {
        int j0 = 2 * kt, j1 = 2 * kt + 1;
        phi[kt][0] = pkh(sacc[j0][0] * inv0, sacc[j0][1] * inv0);
        phi[kt][1] = pkh(sacc[j0][2] * inv1, sacc[j0][3] * inv1);
        phi[kt][2] = pkh(sacc[j1][0] * inv0, sacc[j1][1] * inv0);
        phi[kt][3] = pkh(sacc[j1][2] * inv1, sacc[j1][3] * inv1);
    }

    const float wpv = Wp[0];

    for (int cc = 0; cc < 4; ++cc) {
        if (cc < 3) cp_wait1(); else cp_wait0();
        __syncthreads();
        const uint32_t vs = sb + (cc & 1) * 32768;
        float oacc[8][4];
        #pragma unroll
        for (int j = 0; j < 8; ++j)
            #pragma unroll
            for (int e = 0; e < 4; ++e) oacc[j][e] = 0.0f;

        #pragma unroll
        for (int kt = 0; kt < 8; ++kt) {
            const int vrow = kt * 16 + (lane & 15);
            #pragma unroll
            for (int vc = 0; vc < 4; ++vc) {
                int c16 = vc * 2 + (lane >> 4);
                uint32_t voff = vrow * 128 + ((c16 ^ (vrow & 7)) << 4);
                uint32_t r0, r1, r2, r3;
                ldm_x4_t(r0, r1, r2, r3, vs + voff);
                mmaf16(oacc[2 * vc],     phi[kt], r0, r1);
                mmaf16(oacc[2 * vc + 1], phi[kt], r2, r3);
            }
        }
        __syncthreads();
        if (cc < 2) { loadV(cc & 1, cc + 2); cp_commit(); }  // reuse just-freed stage
        #pragma unroll
        for (int j = 0; j < 8; ++j) {
            int col = j * 8 + t4 * 2;
            *(float2*)&Os[(m0 + g) * 66 + col]     = make_float2(oacc[j][0], oacc[j][1]);
            *(float2*)&Os[(m0 + g + 8) * 66 + col] = make_float2(oacc[j][2], oacc[j][3]);
        }
        __syncthreads();
        #pragma unroll
        for (int it = 0; it < 32; ++it) {
            int idx = it * 256 + tid;
            int c = idx >> 7, w = idx & 127;
            size_t gaddr = (((size_t)b * 256 + cc * 64 + c) * 128 + h) * 128 + w;
            out[gaddr] = a[gaddr] + Os[w * 66 + c] * wpv;
        }
        __syncthreads();
    }
}

extern "C" void kernel_launch(void* const* d_in, const int* in_sizes, int n_in,
                              void* d_out, int out_size)
{
    const float* a  = (const float*)d_in[0];
    const float* wq = (const float*)d_in[1];
    const float* bq = (const float*)d_in[2];
    const float* wk = (const float*)d_in[3];
    const float* bk = (const float*)d_in[4];
    const float* wv = (const float*)d_in[5];
    const float* bv = (const float*)d_in[6];
    const float* Wp = (const float*)d_in[7];
    float* out = (float*)d_out;
    (void)in_sizes; (void)n_in; (void)out_size; (void)bk;

    cudaFuncSetAttribute(tv_mma,   cudaFuncAttributeMaxDynamicSharedMemorySize, TV_SMEM);
    cudaFuncSetAttribute(attn_mma, cudaFuncAttributeMaxDynamicSharedMemorySize, ATTN_SMEM);

    prep<<<33, 256>>>(wq, wk, bq, wv);
    xconvert<<<32768, 256>>>(a);
    tv_mma<<<dim3(4, 1024), 256, TV_SMEM>>>(bv);
    attn_mma<<<1024, 256, ATTN_SMEM>>>(a, Wp, out);
}

// round 14
// speedup vs baseline: 1.5653x; 1.5653x over previous
#include <cuda_runtime.h>
#include <cuda_fp16.h>
#include <stdint.h>
#include <math.h>

#define B_DIM 8
#define C_DIM 256
#define H_DIM 128
#define W_DIM 128
#define HW    (H_DIM * W_DIM)
#define NTOK  (B_DIM * HW)
#define QK_SCALE 0.0625f

// X fp16 c-major: [c][token]
__device__ __half g_x[C_DIM * NTOK];
// T' = X*M + u and V = X*Wv + bv, fp16 [token][channel]
__device__ __half g_t[NTOK * C_DIM];
__device__ __half g_v[NTOK * C_DIM];
// Wv fp16 [o][c]; Mt[c'][c] = scale * sum_o Wq[o,c] Wk[o,c'] fp16; u fp32
__device__ __half g_wv[C_DIM * C_DIM];
__device__ __half g_mt[C_DIM * C_DIM];
__device__ float  g_u[C_DIM];

__device__ __forceinline__ uint32_t smem_u32(const void* p) {
    uint32_t a;
    asm("{ .reg .u64 t; cvta.to.shared.u64 t, %1; cvt.u32.u64 %0, t; }" : "=r"(a) : "l"(p));
    return a;
}
__device__ __forceinline__ void cp16(uint32_t dst, const void* src) {
    asm volatile("cp.async.cg.shared.global [%0], [%1], 16;" :: "r"(dst), "l"(src));
}
__device__ __forceinline__ void cp_commit() { asm volatile("cp.async.commit_group;" ::: "memory"); }
__device__ __forceinline__ void cp_wait1()  { asm volatile("cp.async.wait_group 1;" ::: "memory"); }
__device__ __forceinline__ void cp_wait0()  { asm volatile("cp.async.wait_group 0;" ::: "memory"); }

__device__ __forceinline__ void ldm_x4(uint32_t& r0, uint32_t& r1, uint32_t& r2, uint32_t& r3, uint32_t addr) {
    asm volatile("ldmatrix.sync.aligned.m8n8.x4.shared.b16 {%0,%1,%2,%3}, [%4];"
                 : "=r"(r0), "=r"(r1), "=r"(r2), "=r"(r3) : "r"(addr));
}
__device__ __forceinline__ void ldm_x4_t(uint32_t& r0, uint32_t& r1, uint32_t& r2, uint32_t& r3, uint32_t addr) {
    asm volatile("ldmatrix.sync.aligned.m8n8.x4.trans.shared.b16 {%0,%1,%2,%3}, [%4];"
                 : "=r"(r0), "=r"(r1), "=r"(r2), "=r"(r3) : "r"(addr));
}
__device__ __forceinline__ void mmaf16(float* c, const uint32_t* a, uint32_t b0, uint32_t b1) {
    asm volatile("mma.sync.aligned.m16n8k16.row.col.f32.f16.f16.f32 "
                 "{%0,%1,%2,%3},{%4,%5,%6,%7},{%8,%9},{%0,%1,%2,%3};"
                 : "+f"(c[0]), "+f"(c[1]), "+f"(c[2]), "+f"(c[3])
                 : "r"(a[0]), "r"(a[1]), "r"(a[2]), "r"(a[3]), "r"(b0), "r"(b1));
}
__device__ __forceinline__ uint32_t pkh(float x, float y) {
    __half2 t = __floats2half2_rn(x, y);
    return *(uint32_t*)&t;
}

// Wv fp32 -> fp16
__global__ __launch_bounds__(256)
void wvconvert(const float* __restrict__ wv)
{
    int idx = blockIdx.x * 256 + threadIdx.x;
    g_wv[idx] = __float2half(wv[idx]);
}

// Mt[c'][c] = scale * sum_o Wq[o,c]*Wk[o,c'];  u[c] = scale * sum_o bq[o]*Wk[o,c]
__global__ __launch_bounds__(256)
void mconvert(const float* __restrict__ wq, const float* __restrict__ wk,
              const float* __restrict__ bq)
{
    int cp = blockIdx.x;       // 0..255 => Mt row c'; 256 => u
    int c  = threadIdx.x;
    if (cp < 256) {
        float acc = 0.0f;
        for (int o = 0; o < 256; ++o)
            acc += wq[o * 256 + c] * wk[o * 256 + cp];
        g_mt[cp * 256 + c] = __float2half(acc * QK_SCALE);
    } else {
        float acc = 0.0f;
        for (int o = 0; o < 256; ++o)
            acc += bq[o] * wk[o * 256 + c];
        g_u[c] = acc * QK_SCALE;
    }
}

// a NCHW fp32 -> g_x [c][token] fp16 (coalesced both sides)
__global__ __launch_bounds__(256)
void xconvert(const float* __restrict__ a)
{
    int idx4 = blockIdx.x * 256 + threadIdx.x;
    int b    = idx4 >> 20;
    int rem  = idx4 & 1048575;
    int c    = rem >> 12;
    int hw4  = rem & 4095;
    float4 v = *(const float4*)(a + (size_t)idx4 * 4);
    size_t o = (size_t)c * NTOK + (size_t)b * HW + (size_t)hw4 * 4;
    __half2* ph = (__half2*)(g_x + o);
    ph[0] = __floats2half2_rn(v.x, v.y);
    ph[1] = __floats2half2_rn(v.z, v.w);
}

// ===========================================================================
// T/V GEMM: grid (4,1024). variant: 0,1 = T halves (B=Mt, +u); 2,3 = V halves
// (B=Wv, +bv). CTA 128 tok x 128 out, K=256, double-buffered (R12 structure).
// u folded here: S + 1*gamma^T = (T + 1*u^T) * X^T.
// ===========================================================================
#define TV_STAGE 32768
#define TV_SMEM  65536

__global__ __launch_bounds__(256, 2)
void tv_mma(const float* __restrict__ bv)
{
    extern __shared__ char smem[];
    const uint32_t sb = smem_u32(smem);
    const int tid = threadIdx.x, lane = tid & 31, wid = tid >> 5;
    const int wm0 = (wid & 3) * 32;
    const int wn0 = (wid >> 2) * 64;
    const int variant = blockIdx.x;
    const int half = variant & 1;
    const int isV  = variant >> 1;
    const int tok0 = blockIdx.y * 128;

    const __half* xB = g_x + tok0;
    const __half* wB = (isV ? g_wv : g_mt) + half * 128 * 256;

    const int lrowA = tid >> 4, lc16A = tid & 15;
    const int lrowB = tid >> 3, lc16B = tid & 7;

    auto loadIt = [&](int stg, int kc) {
        const uint32_t st = sb + stg * TV_STAGE;
        const __half* As = xB + (size_t)(kc * 64) * NTOK;
        #pragma unroll
        for (int r = 0; r < 4; ++r) {
            int row = r * 16 + lrowA;
            cp16(st + row * 256 + ((lc16A ^ (row & 7)) << 4),
                 As + (size_t)row * NTOK + lc16A * 8);
        }
        const __half* Bs = wB + kc * 64;
        #pragma unroll
        for (int r = 0; r < 4; ++r) {
            int row = r * 32 + lrowB;
            cp16(st + 16384 + row * 128 + ((lc16B ^ (row & 7)) << 4),
                 Bs + row * 256 + lc16B * 8);
        }
    };

    float acc[2][8][4];
    #pragma unroll
    for (int mt = 0; mt < 2; ++mt)
        #pragma unroll
        for (int n8 = 0; n8 < 8; ++n8)
            #pragma unroll
            for (int e = 0; e < 4; ++e) acc[mt][n8][e] = 0.0f;

    loadIt(0, 0); cp_commit();

    for (int kc = 0; kc < 4; ++kc) {
        if (kc < 3) { loadIt((kc + 1) & 1, kc + 1); cp_commit(); cp_wait1(); }
        else cp_wait0();
        __syncthreads();
        const uint32_t st = sb + (kc & 1) * TV_STAGE;

        #pragma unroll
        for (int ks = 0; ks < 4; ++ks) {
            uint32_t af[2][4];
            const int arow = ks * 16 + (lane & 7) + ((lane >> 4) << 3);
            #pragma unroll
            for (int mt = 0; mt < 2; ++mt) {
                int chunk = (wm0 >> 3) + mt * 2 + ((lane >> 3) & 1);
                uint32_t addr = st + arow * 256 + ((chunk ^ (arow & 7)) << 4);
                ldm_x4_t(af[mt][0], af[mt][1], af[mt][2], af[mt][3], addr);
            }
            const int rbase = (lane & 7) + ((lane >> 3) & 1) * 8;
            const int c16 = ks * 2 + (lane >> 4);
            #pragma unroll
            for (int ng = 0; ng < 4; ++ng) {
                int brow = wn0 + ng * 16 + rbase;
                uint32_t bsw = brow * 128 + ((c16 ^ (brow & 7)) << 4);
                uint32_t b0, b1, b2, b3;
                ldm_x4(b0, b1, b2, b3, st + 16384 + bsw);
                #pragma unroll
                for (int mt = 0; mt < 2; ++mt) {
                    mmaf16(acc[mt][2 * ng],     af[mt], b0, b2);
                    mmaf16(acc[mt][2 * ng + 1], af[mt], b1, b3);
                }
            }
        }
        __syncthreads();
    }

    __half* dst = isV ? g_v : g_t;
    const float* badd = isV ? bv : g_u;
    const int g = lane >> 2, t = lane & 3;
    #pragma unroll
    for (int mt = 0; mt < 2; ++mt) {
        size_t r0 = (size_t)(tok0 + wm0 + mt * 16 + g), r1 = r0 + 8;
        #pragma unroll
        for (int n8 = 0; n8 < 8; ++n8) {
            int o = half * 128 + wn0 + n8 * 8 + t * 2;
            float b0v = badd[o], b1v = badd[o + 1];
            *(uint32_t*)(dst + r0 * 256 + o) = pkh(acc[mt][n8][0] + b0v, acc[mt][n8][1] + b1v);
            *(uint32_t*)(dst + r1 * 256 + o) = pkh(acc[mt][n8][2] + b0v, acc[mt][n8][3] + b1v);
        }
    }
}

// ===========================================================================
// Attention: S = T' * X^T, softmax, O = P * V. One CTA per scanline.
// R12 structure with gamma machinery removed (folded into tv_mma).
// Stages 2x32KB {T 16KB, X 16KB}; V reuses stages; Os fp32 @65536.
// ===========================================================================
#define ATTN_SMEM 99328

__global__ __launch_bounds__(256, 2)
void attn_mma(const float* __restrict__ a, const float* __restrict__ Wp,
              float* __restrict__ out)
{
    extern __shared__ char smem[];
    const uint32_t sb = smem_u32(smem);
    float* Os = (float*)(smem + 65536);
    const int tid = threadIdx.x, lane = tid & 31, wid = tid >> 5;
    const int m0 = wid * 16;
    const int bh = blockIdx.x, b = bh >> 7, h = bh & 127;
    const int tok0 = bh * 128;
    const size_t tokbase = (size_t)bh * 128;

    const int lrow = tid >> 3, lc16 = tid & 7;     // T/V tiles
    const int lrowX = tid >> 4, lc16X = tid & 15;  // X tiles

    auto loadTX = [&](int stg, int kc) {
        const uint32_t st = sb + stg * 32768;
        const size_t scol = tokbase * 256 + kc * 64;
        #pragma unroll
        for (int r = 0; r < 4; ++r) {
            int row = r * 32 + lrow;
            uint32_t doff = row * 128 + ((lc16 ^ (row & 7)) << 4);
            cp16(st + doff, g_t + scol + (size_t)row * 256 + lc16 * 8);
        }
        #pragma unroll
        for (int r = 0; r < 4; ++r) {
            int row = r * 16 + lrowX;
            uint32_t doff = row * 256 + ((lc16X ^ (row & 7)) << 4);
            cp16(st + 16384 + doff,
                 g_x + (size_t)(kc * 64 + row) * NTOK + tok0 + lc16X * 8);
        }
    };
    auto loadV = [&](int stg, int cc) {
        const uint32_t st = sb + stg * 32768;
        const size_t scol = tokbase * 256 + cc * 64;
        #pragma unroll
        for (int r = 0; r < 4; ++r) {
            int row = r * 32 + lrow;
            uint32_t doff = row * 128 + ((lc16 ^ (row & 7)) << 4);
            cp16(st + doff, g_v + scol + (size_t)row * 256 + lc16 * 8);
        }
    };

    float sacc[16][4];
    #pragma unroll
    for (int j = 0; j < 16; ++j)
        #pragma unroll
        for (int e = 0; e < 4; ++e) sacc[j][e] = 0.0f;

    loadTX(0, 0); cp_commit();
    for (int kc = 0; kc < 4; ++kc) {
        if (kc < 3) { loadTX((kc + 1) & 1, kc + 1); cp_commit(); cp_wait1(); }
        else cp_wait0();
        __syncthreads();
        const uint32_t st = sb + (kc & 1) * 32768;
        #pragma unroll
        for (int ks = 0; ks < 4; ++ks) {
            uint32_t ah[4];
            const int c16 = ks * 2 + (lane >> 4);
            int arow = m0 + (lane & 15);
            uint32_t aoff = arow * 128 + ((c16 ^ (arow & 7)) << 4);
            ldm_x4(ah[0], ah[1], ah[2], ah[3], st + aoff);
            const int brow = ks * 16 + (lane & 15);
            #pragma unroll
            for (int bn = 0; bn < 8; ++bn) {
                int nchunk = bn * 2 + (lane >> 4);
                uint32_t boff = brow * 256 + ((nchunk ^ (brow & 7)) << 4);
                uint32_t b0, b1, b2, b3;
                ldm_x4_t(b0, b1, b2, b3, st + 16384 + boff);
                mmaf16(sacc[2 * bn],     ah, b0, b1);
                mmaf16(sacc[2 * bn + 1], ah, b2, b3);
            }
        }
        __syncthreads();
    }
    loadV(0, 0); cp_commit();

    float mx0 = -1e30f, mx1 = -1e30f;
    #pragma unroll
    for (int j = 0; j < 16; ++j) {
        mx0 = fmaxf(mx0, fmaxf(sacc[j][0], sacc[j][1]));
        mx1 = fmaxf(mx1, fmaxf(sacc[j][2], sacc[j][3]));
    }
    mx0 = fmaxf(mx0, __shfl_xor_sync(~0u, mx0, 1));
    mx0 = fmaxf(mx0, __shfl_xor_sync(~0u, mx0, 2));
    mx1 = fmaxf(mx1, __shfl_xor_sync(~0u, mx1, 1));
    mx1 = fmaxf(mx1, __shfl_xor_sync(~0u, mx1, 2));
    float sum0 = 0.0f, sum1 = 0.0f;
    #pragma unroll
    for (int j = 0; j < 16; ++j) {
        sacc[j][0] = __expf(sacc[j][0] - mx0); sum0 += sacc[j][0];
        sacc[j][1] = __expf(sacc[j][1] - mx0); sum0 += sacc[j][1];
        sacc[j][2] = __expf(sacc[j][2] - mx1); sum1 += sacc[j][2];
        sacc[j][3] = __expf(sacc[j][3] - mx1); sum1 += sacc[j][3];
    }
    sum0 += __shfl_xor_sync(~0u, sum0, 1);
    sum0 += __shfl_xor_sync(~0u, sum0, 2);
    sum1 += __shfl_xor_sync(~0u, sum1, 1);
    sum1 += __shfl_xor_sync(~0u, sum1, 2);
    const float inv0 = 1.0f / sum0, inv1 = 1.0f / sum1;

    uint32_t phi[8][4];
    #pragma unroll
    for (int kt = 0; kt < 8; ++kt) {
        int j0 = 2 * kt, j1 = 2 * kt + 1;
        phi[kt][0] = pkh(sacc[j0][0] * inv0, sacc[j0][1] * inv0);
        phi[kt][1] = pkh(sacc[j0][2] * inv1, sacc[j0][3] * inv1);
        phi[kt][2] = pkh(sacc[j1][0] * inv0, sacc[j1][1] * inv0);
        phi[kt][3] = pkh(sacc[j1][2] * inv1, sacc[j1][3] * inv1);
    }

    const float wpv = Wp[0];
    const int g = lane >> 2, t4 = lane & 3;

    for (int cc = 0; cc < 4; ++cc) {
        if (cc < 3) { loadV((cc + 1) & 1, cc + 1); cp_commit(); cp_wait1(); }
        else cp_wait0();
        __syncthreads();
        const uint32_t vs = sb + (cc & 1) * 32768;
        float oacc[8][4];
        #pragma unroll
        for (int j = 0; j < 8; ++j)
            #pragma unroll
            for (int e = 0; e < 4; ++e) oacc[j][e] = 0.0f;

        #pragma unroll
        for (int kt = 0; kt < 8; ++kt) {
            const int vrow = kt * 16 + (lane & 15);
            #pragma unroll
            for (int vc = 0; vc < 4; ++vc) {
                int c16 = vc * 2 + (lane >> 4);
                uint32_t voff = vrow * 128 + ((c16 ^ (vrow & 7)) << 4);
                uint32_t r0, r1, r2, r3;
                ldm_x4_t(r0, r1, r2, r3, vs + voff);
                mmaf16(oacc[2 * vc],     phi[kt], r0, r1);
                mmaf16(oacc[2 * vc + 1], phi[kt], r2, r3);
            }
        }
        __syncthreads();
        #pragma unroll
        for (int j = 0; j < 8; ++j) {
            int col = j * 8 + t4 * 2;
            *(float2*)&Os[(m0 + g) * 66 + col]     = make_float2(oacc[j][0], oacc[j][1]);
            *(float2*)&Os[(m0 + g + 8) * 66 + col] = make_float2(oacc[j][2], oacc[j][3]);
        }
        __syncthreads();
        #pragma unroll
        for (int it = 0; it < 32; ++it) {
            int idx = it * 256 + tid;
            int c = idx >> 7, w = idx & 127;
            size_t gaddr = (((size_t)b * 256 + cc * 64 + c) * 128 + h) * 128 + w;
            out[gaddr] = a[gaddr] + Os[w * 66 + c] * wpv;
        }
        __syncthreads();
    }
}

extern "C" void kernel_launch(void* const* d_in, const int* in_sizes, int n_in,
                              void* d_out, int out_size)
{
    const float* a  = (const float*)d_in[0];
    const float* wq = (const float*)d_in[1];
    const float* bq = (const float*)d_in[2];
    const float* wk = (const float*)d_in[3];
    const float* bk = (const float*)d_in[4];
    const float* wv = (const float*)d_in[5];
    const float* bv = (const float*)d_in[6];
    const float* Wp = (const float*)d_in[7];
    float* out = (float*)d_out;
    (void)in_sizes; (void)n_in; (void)out_size; (void)bk;

    cudaFuncSetAttribute(tv_mma,   cudaFuncAttributeMaxDynamicSharedMemorySize, TV_SMEM);
    cudaFuncSetAttribute(attn_mma, cudaFuncAttributeMaxDynamicSharedMemorySize, ATTN_SMEM);

    wvconvert<<<256, 256>>>(wv);
    mconvert<<<257, 256>>>(wq, wk, bq);
    xconvert<<<32768, 256>>>(a);
    tv_mma<<<dim3(4, 1024), 256, TV_SMEM>>>(bv);
    attn_mma<<<1024, 256, ATTN_SMEM>>>(a, Wp, out);
}

// round 16
// speedup vs baseline: 1.7127x; 1.0942x over previous
#include <cuda_runtime.h>
#include <cuda_fp16.h>
#include <stdint.h>
#include <math.h>

#define B_DIM 8
#define C_DIM 256
#define H_DIM 128
#define W_DIM 128
#define HW    (H_DIM * W_DIM)
#define NTOK  (B_DIM * HW)
#define QK_SCALE 0.0625f

// X fp16 c-major: [c][token]
__device__ __half g_x[C_DIM * NTOK];
// T' = X*M + u and V = X*Wv + bv, fp16 [token][channel]
__device__ __half g_t[NTOK * C_DIM];
__device__ __half g_v[NTOK * C_DIM];
// Wv fp16 [o][c]; Mt[c'][c] = scale * sum_o Wq[o,c] Wk[o,c'] fp16; u fp32
__device__ __half g_wv[C_DIM * C_DIM];
__device__ __half g_mt[C_DIM * C_DIM];
__device__ float  g_u[C_DIM];

__device__ __forceinline__ uint32_t smem_u32(const void* p) {
    uint32_t a;
    asm("{ .reg .u64 t; cvta.to.shared.u64 t, %1; cvt.u32.u64 %0, t; }" : "=r"(a) : "l"(p));
    return a;
}
__device__ __forceinline__ void cp16(uint32_t dst, const void* src) {
    asm volatile("cp.async.cg.shared.global [%0], [%1], 16;" :: "r"(dst), "l"(src));
}
__device__ __forceinline__ void cp_commit() { asm volatile("cp.async.commit_group;" ::: "memory"); }
__device__ __forceinline__ void cp_wait1()  { asm volatile("cp.async.wait_group 1;" ::: "memory"); }
__device__ __forceinline__ void cp_wait0()  { asm volatile("cp.async.wait_group 0;" ::: "memory"); }

__device__ __forceinline__ void ldm_x4(uint32_t& r0, uint32_t& r1, uint32_t& r2, uint32_t& r3, uint32_t addr) {
    asm volatile("ldmatrix.sync.aligned.m8n8.x4.shared.b16 {%0,%1,%2,%3}, [%4];"
                 : "=r"(r0), "=r"(r1), "=r"(r2), "=r"(r3) : "r"(addr));
}
__device__ __forceinline__ void ldm_x4_t(uint32_t& r0, uint32_t& r1, uint32_t& r2, uint32_t& r3, uint32_t addr) {
    asm volatile("ldmatrix.sync.aligned.m8n8.x4.trans.shared.b16 {%0,%1,%2,%3}, [%4];"
                 : "=r"(r0), "=r"(r1), "=r"(r2), "=r"(r3) : "r"(addr));
}
__device__ __forceinline__ void mmaf16(float* c, const uint32_t* a, uint32_t b0, uint32_t b1) {
    asm volatile("mma.sync.aligned.m16n8k16.row.col.f32.f16.f16.f32 "
                 "{%0,%1,%2,%3},{%4,%5,%6,%7},{%8,%9},{%0,%1,%2,%3};"
                 : "+f"(c[0]), "+f"(c[1]), "+f"(c[2]), "+f"(c[3])
                 : "r"(a[0]), "r"(a[1]), "r"(a[2]), "r"(a[3]), "r"(b0), "r"(b1));
}
__device__ __forceinline__ uint32_t pkh(float x, float y) {
    __half2 t = __floats2half2_rn(x, y);
    return *(uint32_t*)&t;
}

// ===========================================================================
// Fused prep + xconvert. Heavy blocks FIRST (no tail):
//   blk 0..255   : Mt row cp = blk (+ wv row convert)
//   blk 256      : u vector
//   blk 257..    : xconvert tile (blk - 257)
// ===========================================================================
__global__ __launch_bounds__(256)
void convert_all(const float* __restrict__ a,
                 const float* __restrict__ wq, const float* __restrict__ wk,
                 const float* __restrict__ bq, const float* __restrict__ wv)
{
    int blk = blockIdx.x;
    int c = threadIdx.x;
    if (blk < 256) {
        int cp = blk;
        float acc = 0.0f;
        for (int o = 0; o < 256; ++o)
            acc += wq[o * 256 + c] * wk[o * 256 + cp];
        g_mt[cp * 256 + c] = __float2half(acc * QK_SCALE);
        g_wv[cp * 256 + c] = __float2half(wv[cp * 256 + c]);
        return;
    }
    if (blk == 256) {
        float acc = 0.0f;
        for (int o = 0; o < 256; ++o)
            acc += bq[o] * wk[o * 256 + c];
        g_u[c] = acc * QK_SCALE;
        return;
    }
    int idx4 = (blk - 257) * 256 + c;
    int b    = idx4 >> 20;
    int rem  = idx4 & 1048575;
    int cc   = rem >> 12;
    int hw4  = rem & 4095;
    float4 v = *(const float4*)(a + (size_t)idx4 * 4);
    size_t o = (size_t)cc * NTOK + (size_t)b * HW + (size_t)hw4 * 4;
    __half2* ph = (__half2*)(g_x + o);
    ph[0] = __floats2half2_rn(v.x, v.y);
    ph[1] = __floats2half2_rn(v.z, v.w);
}

// ===========================================================================
// T/V GEMM: grid (4,1024). variant: 0,1 = T halves (B=Mt, +u); 2,3 = V halves
// (B=Wv, +bv). CTA 128 tok x 128 out, K=256, double-buffered.
// ===========================================================================
#define TV_STAGE 32768
#define TV_SMEM  65536

__global__ __launch_bounds__(256, 2)
void tv_mma(const float* __restrict__ bv)
{
    extern __shared__ char smem[];
    const uint32_t sb = smem_u32(smem);
    const int tid = threadIdx.x, lane = tid & 31, wid = tid >> 5;
    const int wm0 = (wid & 3) * 32;
    const int wn0 = (wid >> 2) * 64;
    const int variant = blockIdx.x;
    const int half = variant & 1;
    const int isV  = variant >> 1;
    const int tok0 = blockIdx.y * 128;

    const __half* xB = g_x + tok0;
    const __half* wB = (isV ? g_wv : g_mt) + half * 128 * 256;

    const int lrowA = tid >> 4, lc16A = tid & 15;
    const int lrowB = tid >> 3, lc16B = tid & 7;

    auto loadIt = [&](int stg, int kc) {
        const uint32_t st = sb + stg * TV_STAGE;
        const __half* As = xB + (size_t)(kc * 64) * NTOK;
        #pragma unroll
        for (int r = 0; r < 4; ++r) {
            int row = r * 16 + lrowA;
            cp16(st + row * 256 + ((lc16A ^ (row & 7)) << 4),
                 As + (size_t)row * NTOK + lc16A * 8);
        }
        const __half* Bs = wB + kc * 64;
        #pragma unroll
        for (int r = 0; r < 4; ++r) {
            int row = r * 32 + lrowB;
            cp16(st + 16384 + row * 128 + ((lc16B ^ (row & 7)) << 4),
                 Bs + row * 256 + lc16B * 8);
        }
    };

    float acc[2][8][4];
    #pragma unroll
    for (int mt = 0; mt < 2; ++mt)
        #pragma unroll
        for (int n8 = 0; n8 < 8; ++n8)
            #pragma unroll
            for (int e = 0; e < 4; ++e) acc[mt][n8][e] = 0.0f;

    loadIt(0, 0); cp_commit();

    for (int kc = 0; kc < 4; ++kc) {
        if (kc < 3) { loadIt((kc + 1) & 1, kc + 1); cp_commit(); cp_wait1(); }
        else cp_wait0();
        __syncthreads();
        const uint32_t st = sb + (kc & 1) * TV_STAGE;

        #pragma unroll
        for (int ks = 0; ks < 4; ++ks) {
            uint32_t af[2][4];
            const int arow = ks * 16 + (lane & 7) + ((lane >> 4) << 3);
            #pragma unroll
            for (int mt = 0; mt < 2; ++mt) {
                int chunk = (wm0 >> 3) + mt * 2 + ((lane >> 3) & 1);
                uint32_t addr = st + arow * 256 + ((chunk ^ (arow & 7)) << 4);
                ldm_x4_t(af[mt][0], af[mt][1], af[mt][2], af[mt][3], addr);
            }
            const int rbase = (lane & 7) + ((lane >> 3) & 1) * 8;
            const int c16 = ks * 2 + (lane >> 4);
            #pragma unroll
            for (int ng = 0; ng < 4; ++ng) {
                int brow = wn0 + ng * 16 + rbase;
                uint32_t bsw = brow * 128 + ((c16 ^ (brow & 7)) << 4);
                uint32_t b0, b1, b2, b3;
                ldm_x4(b0, b1, b2, b3, st + 16384 + bsw);
                #pragma unroll
                for (int mt = 0; mt < 2; ++mt) {
                    mmaf16(acc[mt][2 * ng],     af[mt], b0, b2);
                    mmaf16(acc[mt][2 * ng + 1], af[mt], b1, b3);
                }
            }
        }
        __syncthreads();
    }

    __half* dst = isV ? g_v : g_t;
    const float* badd = isV ? bv : g_u;
    const int g = lane >> 2, t = lane & 3;
    #pragma unroll
    for (int mt = 0; mt < 2; ++mt) {
        size_t r0 = (size_t)(tok0 + wm0 + mt * 16 + g), r1 = r0 + 8;
        #pragma unroll
        for (int n8 = 0; n8 < 8; ++n8) {
            int o = half * 128 + wn0 + n8 * 8 + t * 2;
            float b0v = badd[o], b1v = badd[o + 1];
            *(uint32_t*)(dst + r0 * 256 + o) = pkh(acc[mt][n8][0] + b0v, acc[mt][n8][1] + b1v);
            *(uint32_t*)(dst + r1 * 256 + o) = pkh(acc[mt][n8][2] + b0v, acc[mt][n8][3] + b1v);
        }
    }
}

// ===========================================================================
// Attention: S = T' * X^T, softmax, O = P * V (Wp folded into P).
// One CTA per scanline. Stages 2x32KB; Os fp32 @65536.
// ===========================================================================
#define ATTN_SMEM 99328

__global__ __launch_bounds__(256, 2)
void attn_mma(const float* __restrict__ a, const float* __restrict__ Wp,
              float* __restrict__ out)
{
    extern __shared__ char smem[];
    const uint32_t sb = smem_u32(smem);
    float* Os = (float*)(smem + 65536);
    const int tid = threadIdx.x, lane = tid & 31, wid = tid >> 5;
    const int m0 = wid * 16;
    const int bh = blockIdx.x, b = bh >> 7, h = bh & 127;
    const int tok0 = bh * 128;
    const size_t tokbase = (size_t)bh * 128;

    const int lrow = tid >> 3, lc16 = tid & 7;     // T/V tiles
    const int lrowX = tid >> 4, lc16X = tid & 15;  // X tiles

    auto loadTX = [&](int stg, int kc) {
        const uint32_t st = sb + stg * 32768;
        const size_t scol = tokbase * 256 + kc * 64;
        #pragma unroll
        for (int r = 0; r < 4; ++r) {
            int row = r * 32 + lrow;
            uint32_t doff = row * 128 + ((lc16 ^ (row & 7)) << 4);
            cp16(st + doff, g_t + scol + (size_t)row * 256 + lc16 * 8);
        }
        #pragma unroll
        for (int r = 0; r < 4; ++r) {
            int row = r * 16 + lrowX;
            uint32_t doff = row * 256 + ((lc16X ^ (row & 7)) << 4);
            cp16(st + 16384 + doff,
                 g_x + (size_t)(kc * 64 + row) * NTOK + tok0 + lc16X * 8);
        }
    };
    auto loadV = [&](int stg, int cc) {
        const uint32_t st = sb + stg * 32768;
        const size_t scol = tokbase * 256 + cc * 64;
        #pragma unroll
        for (int r = 0; r < 4; ++r) {
            int row = r * 32 + lrow;
            uint32_t doff = row * 128 + ((lc16 ^ (row & 7)) << 4);
            cp16(st + doff, g_v + scol + (size_t)row * 256 + lc16 * 8);
        }
    };

    float sacc[16][4];
    #pragma unroll
    for (int j = 0; j < 16; ++j)
        #pragma unroll
        for (int e = 0; e < 4; ++e) sacc[j][e] = 0.0f;

    loadTX(0, 0); cp_commit();
    for (int kc = 0; kc < 4; ++kc) {
        if (kc < 3) { loadTX((kc + 1) & 1, kc + 1); cp_commit(); cp_wait1(); }
        else cp_wait0();
        __syncthreads();
        const uint32_t st = sb + (kc & 1) * 32768;
        #pragma unroll
        for (int ks = 0; ks < 4; ++ks) {
            uint32_t ah[4];
            const int c16 = ks * 2 + (lane >> 4);
            int arow = m0 + (lane & 15);
            uint32_t aoff = arow * 128 + ((c16 ^ (arow & 7)) << 4);
            ldm_x4(ah[0], ah[1], ah[2], ah[3], st + aoff);
            const int brow = ks * 16 + (lane & 15);
            #pragma unroll
            for (int bn = 0; bn < 8; ++bn) {
                int nchunk = bn * 2 + (lane >> 4);
                uint32_t boff = brow * 256 + ((nchunk ^ (brow & 7)) << 4);
                uint32_t b0, b1, b2, b3;
                ldm_x4_t(b0, b1, b2, b3, st + 16384 + boff);
                mmaf16(sacc[2 * bn],     ah, b0, b1);
                mmaf16(sacc[2 * bn + 1], ah, b2, b3);
            }
        }
        __syncthreads();
    }
    loadV(0, 0); cp_commit();

    float mx0 = -1e30f, mx1 = -1e30f;
    #pragma unroll
    for (int j = 0; j < 16; ++j) {
        mx0 = fmaxf(mx0, fmaxf(sacc[j][0], sacc[j][1]));
        mx1 = fmaxf(mx1, fmaxf(sacc[j][2], sacc[j][3]));
    }
    mx0 = fmaxf(mx0, __shfl_xor_sync(~0u, mx0, 1));
    mx0 = fmaxf(mx0, __shfl_xor_sync(~0u, mx0, 2));
    mx1 = fmaxf(mx1, __shfl_xor_sync(~0u, mx1, 1));
    mx1 = fmaxf(mx1, __shfl_xor_sync(~0u, mx1, 2));
    float sum0 = 0.0f, sum1 = 0.0f;
    #pragma unroll
    for (int j = 0; j < 16; ++j) {
        sacc[j][0] = __expf(sacc[j][0] - mx0); sum0 += sacc[j][0];
        sacc[j][1] = __expf(sacc[j][1] - mx0); sum0 += sacc[j][1];
        sacc[j][2] = __expf(sacc[j][2] - mx1); sum1 += sacc[j][2];
        sacc[j][3] = __expf(sacc[j][3] - mx1); sum1 += sacc[j][3];
    }
    sum0 += __shfl_xor_sync(~0u, sum0, 1);
    sum0 += __shfl_xor_sync(~0u, sum0, 2);
    sum1 += __shfl_xor_sync(~0u, sum1, 1);
    sum1 += __shfl_xor_sync(~0u, sum1, 2);

    // Fold Wp into P: O_scaled = (P*wpv) . V ; epilogue adds a only.
    const float wpv = Wp[0];
    const float inv0 = wpv / sum0, inv1 = wpv / sum1;

    uint32_t phi[8][4];
    #pragma unroll
    for (int kt = 0; kt < 8; ++kt) {
        int j0 = 2 * kt, j1 = 2 * kt + 1;
        phi[kt][0] = pkh(sacc[j0][0] * inv0, sacc[j0][1] * inv0);
        phi[kt][1] = pkh(sacc[j0][2] * inv1, sacc[j0][3] * inv1);
        phi[kt][2] = pkh(sacc[j1][0] * inv0, sacc[j1][1] * inv0);
        phi[kt][3] = pkh(sacc[j1][2] * inv1, sacc[j1][3] * inv1);
    }

    const int g = lane >> 2, t4 = lane & 3;

    for (int cc = 0; cc < 4; ++cc) {
        if (cc < 3) { loadV((cc + 1) & 1, cc + 1); cp_commit(); cp_wait1(); }
        else cp_wait0();
        __syncthreads();
        const uint32_t vs = sb + (cc & 1) * 32768;
        float oacc[8][4];
        #pragma unroll
        for (int j = 0; j < 8; ++j)
            #pragma unroll
            for (int e = 0; e < 4; ++e) oacc[j][e] = 0.0f;

        #pragma unroll
        for (int kt = 0; kt < 8; ++kt) {
            const int vrow = kt * 16 + (lane & 15);
            #pragma unroll
            for (int vc = 0; vc < 4; ++vc) {
                int c16 = vc * 2 + (lane >> 4);
                uint32_t voff = vrow * 128 + ((c16 ^ (vrow & 7)) << 4);
                uint32_t r0, r1, r2, r3;
                ldm_x4_t(r0, r1, r2, r3, vs + voff);
                mmaf16(oacc[2 * vc],     phi[kt], r0, r1);
                mmaf16(oacc[2 * vc + 1], phi[kt], r2, r3);
            }
        }
        // no barrier needed: Os region is disjoint from V stages, and the
        // loop-end barrier already ordered prior Os readers before these writes
        #pragma unroll
        for (int j = 0; j < 8; ++j) {
            int col = j * 8 + t4 * 2;
            *(float2*)&Os[(m0 + g) * 66 + col]     = make_float2(oacc[j][0], oacc[j][1]);
            *(float2*)&Os[(m0 + g + 8) * 66 + col] = make_float2(oacc[j][2], oacc[j][3]);
        }
        __syncthreads();
        #pragma unroll
        for (int it = 0; it < 32; ++it) {
            int idx = it * 256 + tid;
            int c = idx >> 7, w = idx & 127;
            size_t gaddr = (((size_t)b * 256 + cc * 64 + c) * 128 + h) * 128 + w;
            out[gaddr] = a[gaddr] + Os[w * 66 + c];
        }
        __syncthreads();
    }
}

extern "C" void kernel_launch(void* const* d_in, const int* in_sizes, int n_in,
                              void* d_out, int out_size)
{
    const float* a  = (const float*)d_in[0];
    const float* wq = (const float*)d_in[1];
    const float* bq = (const float*)d_in[2];
    const float* wk = (const float*)d_in[3];
    const float* bk = (const float*)d_in[4];
    const float* wv = (const float*)d_in[5];
    const float* bv = (const float*)d_in[6];
    const float* Wp = (const float*)d_in[7];
    float* out = (float*)d_out;
    (void)in_sizes; (void)n_in; (void)out_size; (void)bk;

    cudaFuncSetAttribute(tv_mma,   cudaFuncAttributeMaxDynamicSharedMemorySize, TV_SMEM);
    cudaFuncSetAttribute(attn_mma, cudaFuncAttributeMaxDynamicSharedMemorySize, ATTN_SMEM);

    convert_all<<<33025, 256>>>(a, wq, wk, bq, wv);
    tv_mma<<<dim3(4, 1024), 256, TV_SMEM>>>(bv);
    attn_mma<<<1024, 256, ATTN_SMEM>>>(a, Wp, out);
}